// round 1
// baseline (speedup 1.0000x reference)
#include <cuda_runtime.h>
#include <cstdint>
#include <cstddef>

// ---------------- problem constants ----------------
#define BB   16
#define NN   784
#define CC   384
#define HEADS 8
#define DH   48
#define HID  1536
#define RD   96
#define HH   28
#define WW   28
#define ROWS (BB*NN)          // 12544
#define BH   (BB*HEADS)       // 128

// ---------------- scratch (static device memory; allocation-free) ----------------
__device__ float g_h1[(size_t)ROWS*CC];
__device__ float g_q [(size_t)ROWS*CC];
__device__ float g_kv[(size_t)ROWS*2*CC];
__device__ float g_S [(size_t)BH*NN*NN];     // 314.7 MB attention logits
__device__ float g_o [(size_t)ROWS*CC];
__device__ float g_x1[(size_t)ROWS*CC];
__device__ float g_h2[(size_t)ROWS*CC];
__device__ float g_u [(size_t)ROWS*HID];
__device__ float g_hb[(size_t)ROWS*HID];
__device__ float g_y [(size_t)ROWS*CC];
__device__ float g_s0[BB*CC];
__device__ float g_s2[BB*CC];

// ---------------- LayerNorm: one CTA (128 thr) per row of 384 ----------------
__global__ void __launch_bounds__(128) ln_k(const float* __restrict__ x,
                                            const float* __restrict__ g,
                                            const float* __restrict__ be,
                                            float* __restrict__ y)
{
    const int row = blockIdx.x;
    const int tid = threadIdx.x;
    const float* xr = x + (size_t)row * CC;
    float a = xr[tid], b2 = xr[tid+128], c = xr[tid+256];
    float s = a + b2 + c;
    float ss = a*a + b2*b2 + c*c;
    #pragma unroll
    for (int o = 16; o; o >>= 1) {
        s  += __shfl_xor_sync(0xffffffffu, s,  o);
        ss += __shfl_xor_sync(0xffffffffu, ss, o);
    }
    __shared__ float rs[4], rss[4];
    if ((tid & 31) == 0) { rs[tid>>5] = s; rss[tid>>5] = ss; }
    __syncthreads();
    s  = rs[0]+rs[1]+rs[2]+rs[3];
    ss = rss[0]+rss[1]+rss[2]+rss[3];
    const float m   = s * (1.f/CC);
    const float var = ss * (1.f/CC) - m*m;
    const float r   = rsqrtf(var + 1e-5f);
    float* yr = y + (size_t)row * CC;
    yr[tid]     = (a  - m)*r*g[tid]     + be[tid];
    yr[tid+128] = (b2 - m)*r*g[tid+128] + be[tid+128];
    yr[tid+256] = (c  - m)*r*g[tid+256] + be[tid+256];
}

// ---------------- 128x128x8 SGEMM, fp32, double-buffered ----------------
// C[M,N] = A[M,K] @ B[K,N] + bias[N]          (MODE 0)
// C[M,N] = res[M,N] + gamma[N]*(A@B + bias)   (MODE 1)
// requires M%128==0, N%128==0, K%8==0 (true for all uses here)
template<int MODE>
__global__ void __launch_bounds__(256, 2) sgemm_k(const float* __restrict__ A,
                                                  const float* __restrict__ B,
                                                  const float* __restrict__ bias,
                                                  const float* __restrict__ res,
                                                  const float* __restrict__ gamma,
                                                  float* __restrict__ C,
                                                  int M, int N, int K)
{
    __shared__ float As[2][8][128];
    __shared__ float Bs[2][8][128];
    const int tid = threadIdx.x;
    const int m0 = blockIdx.y * 128, n0 = blockIdx.x * 128;
    const int arow = tid >> 1, acol = (tid & 1) << 2;
    const int brow = tid >> 5, bcol = (tid & 31) << 2;
    const float* Ap = A + (size_t)(m0 + arow) * K + acol;
    const float* Bp = B + (size_t)brow * N + n0 + bcol;

    float4 av = *(const float4*)Ap;
    float4 bv = *(const float4*)Bp;
    As[0][acol+0][arow] = av.x; As[0][acol+1][arow] = av.y;
    As[0][acol+2][arow] = av.z; As[0][acol+3][arow] = av.w;
    *(float4*)&Bs[0][brow][bcol] = bv;
    __syncthreads();

    const int tx = (tid & 15) << 3, ty = (tid >> 4) << 3;
    float acc[8][8] = {};
    const int nk = K >> 3;
    for (int t = 1; t <= nk; t++) {
        const int cur = (t - 1) & 1, nxt = t & 1;
        if (t < nk) {
            av = *(const float4*)(Ap + t * 8);
            bv = *(const float4*)(Bp + (size_t)t * 8 * N);
        }
        #pragma unroll
        for (int kk = 0; kk < 8; kk++) {
            float af[8], bf[8];
            *(float4*)&af[0] = *(const float4*)&As[cur][kk][ty];
            *(float4*)&af[4] = *(const float4*)&As[cur][kk][ty+4];
            *(float4*)&bf[0] = *(const float4*)&Bs[cur][kk][tx];
            *(float4*)&bf[4] = *(const float4*)&Bs[cur][kk][tx+4];
            #pragma unroll
            for (int i = 0; i < 8; i++)
                #pragma unroll
                for (int j = 0; j < 8; j++)
                    acc[i][j] = fmaf(af[i], bf[j], acc[i][j]);
        }
        if (t < nk) {
            As[nxt][acol+0][arow] = av.x; As[nxt][acol+1][arow] = av.y;
            As[nxt][acol+2][arow] = av.z; As[nxt][acol+3][arow] = av.w;
            *(float4*)&Bs[nxt][brow][bcol] = bv;
        }
        __syncthreads();
    }

    #pragma unroll
    for (int i = 0; i < 8; i++) {
        const int m = m0 + ty + i;
        #pragma unroll
        for (int j = 0; j < 8; j++) {
            const int n = n0 + tx + j;
            float v = acc[i][j] + bias[n];
            if (MODE == 1) v = res[(size_t)m * N + n] + gamma[n] * v;
            C[(size_t)m * N + n] = v;
        }
    }
}

// ---------------- attention: S = scale * q @ k^T, batched over (b,h) ----------------
__global__ void __launch_bounds__(256) attn_scores_k(const float* __restrict__ qg,
                                                     const float* __restrict__ kvg,
                                                     float* __restrict__ S)
{
    __shared__ float qs[DH][64];
    __shared__ float ks[DH][64];
    const int tid = threadIdx.x;
    const int bh = blockIdx.z, b = bh >> 3, h = bh & 7;
    const int q0 = blockIdx.x * 64, k0 = blockIdx.y * 64;
    const float scale = rsqrtf((float)DH);

    for (int e = tid; e < 64 * DH; e += 256) {
        const int r = e / DH, c = e % DH;
        const int qn = q0 + r, kn = k0 + r;
        qs[c][r] = (qn < NN) ? qg[((size_t)b*NN + qn)*CC + h*DH + c] * scale : 0.f;
        ks[c][r] = (kn < NN) ? kvg[((size_t)b*NN + kn)*2*CC + h*DH + c] : 0.f;
    }
    __syncthreads();

    const int tx = (tid & 15) << 2, ty = (tid >> 4) << 2;
    float acc[4][4] = {};
    #pragma unroll
    for (int kk = 0; kk < DH; kk++) {
        float af[4], bf[4];
        *(float4*)af = *(const float4*)&qs[kk][ty];
        *(float4*)bf = *(const float4*)&ks[kk][tx];
        #pragma unroll
        for (int i = 0; i < 4; i++)
            #pragma unroll
            for (int j = 0; j < 4; j++)
                acc[i][j] = fmaf(af[i], bf[j], acc[i][j]);
    }
    #pragma unroll
    for (int i = 0; i < 4; i++) {
        const int qn = q0 + ty + i;
        if (qn >= NN) continue;
        #pragma unroll
        for (int j = 0; j < 4; j++) {
            const int kn = k0 + tx + j;
            if (kn < NN) S[((size_t)bh*NN + qn)*NN + kn] = acc[i][j];
        }
    }
}

// ---------------- softmax over last dim (784), in place ----------------
__global__ void __launch_bounds__(256) softmax_k(float* __restrict__ S)
{
    const size_t row = (size_t)blockIdx.y * NN + blockIdx.x;
    float* p = S + row * NN;
    const int tid = threadIdx.x;
    float v[4];
    int ne = 0;
    float mx = -1e30f;
    for (int i = tid; i < NN; i += 256) { v[ne] = p[i]; mx = fmaxf(mx, v[ne]); ne++; }
    #pragma unroll
    for (int o = 16; o; o >>= 1) mx = fmaxf(mx, __shfl_xor_sync(0xffffffffu, mx, o));
    __shared__ float red[8];
    if ((tid & 31) == 0) red[tid >> 5] = mx;
    __syncthreads();
    if (tid == 0) {
        float m = red[0];
        #pragma unroll
        for (int w = 1; w < 8; w++) m = fmaxf(m, red[w]);
        red[0] = m;
    }
    __syncthreads();
    mx = red[0];
    __syncthreads();
    float s = 0.f;
    for (int e = 0; e < ne; e++) { v[e] = __expf(v[e] - mx); s += v[e]; }
    #pragma unroll
    for (int o = 16; o; o >>= 1) s += __shfl_xor_sync(0xffffffffu, s, o);
    if ((tid & 31) == 0) red[tid >> 5] = s;
    __syncthreads();
    if (tid == 0) {
        float t = 0.f;
        #pragma unroll
        for (int w = 0; w < 8; w++) t += red[w];
        red[0] = t;
    }
    __syncthreads();
    const float inv = 1.f / red[0];
    int e = 0;
    for (int i = tid; i < NN; i += 256) p[i] = v[e++] * inv;
}

// ---------------- attention: O = P @ V, writes [b,n,h*48+d] layout ----------------
__global__ void __launch_bounds__(256) attn_av_k(const float* __restrict__ S,
                                                 const float* __restrict__ kvg,
                                                 float* __restrict__ o)
{
    __shared__ float Ps[64][65];   // [kk][row], padded
    __shared__ float Vs[64][DH];
    const int tid = threadIdx.x;
    const int bh = blockIdx.y, b = bh >> 3, h = bh & 7;
    const int q0 = blockIdx.x * 64;
    const int tx = (tid & 15) * 3, ty = (tid >> 4) << 2;
    float acc[4][3] = {};

    for (int kc = 0; kc < NN; kc += 64) {
        #pragma unroll
        for (int e = 0; e < 16; e++) {
            const int idx = tid + e * 256;
            const int r = idx >> 6, cc = idx & 63;
            const int qn = q0 + r, kn = kc + cc;
            Ps[cc][r] = (qn < NN && kn < NN) ? S[((size_t)bh*NN + qn)*NN + kn] : 0.f;
        }
        #pragma unroll
        for (int e = 0; e < 12; e++) {
            const int idx = tid + e * 256;
            const int r = idx / DH, cc = idx % DH;
            const int kn = kc + r;
            Vs[r][cc] = (kn < NN) ? kvg[((size_t)b*NN + kn)*2*CC + CC + h*DH + cc] : 0.f;
        }
        __syncthreads();
        #pragma unroll 8
        for (int kk = 0; kk < 64; kk++) {
            float pf[4], vf[3];
            pf[0] = Ps[kk][ty];   pf[1] = Ps[kk][ty+1];
            pf[2] = Ps[kk][ty+2]; pf[3] = Ps[kk][ty+3];
            vf[0] = Vs[kk][tx]; vf[1] = Vs[kk][tx+1]; vf[2] = Vs[kk][tx+2];
            #pragma unroll
            for (int i = 0; i < 4; i++)
                #pragma unroll
                for (int j = 0; j < 3; j++)
                    acc[i][j] = fmaf(pf[i], vf[j], acc[i][j]);
        }
        __syncthreads();
    }
    #pragma unroll
    for (int i = 0; i < 4; i++) {
        const int qn = q0 + ty + i;
        if (qn >= NN) continue;
        #pragma unroll
        for (int j = 0; j < 3; j++)
            o[((size_t)b*NN + qn)*CC + h*DH + tx + j] = acc[i][j];
    }
}

// ---------------- depthwise 3x3 conv + bias + mlp_gamma*dw + u ----------------
__global__ void __launch_bounds__(256) dwconv_k(const float* __restrict__ u,
                                                const float* __restrict__ w,
                                                const float* __restrict__ wb,
                                                const float* __restrict__ mg,
                                                float* __restrict__ hb)
{
    const int n = blockIdx.x, b = blockIdx.y;
    const int hy = n / WW, wx = n % WW;
    const float* ub = u + (size_t)b * NN * HID;
    for (int ch = threadIdx.x; ch < HID; ch += 256) {
        float acc = wb[ch];
        #pragma unroll
        for (int dy = -1; dy <= 1; dy++) {
            const int yy = hy + dy;
            if (yy < 0 || yy >= HH) continue;
            #pragma unroll
            for (int dx = -1; dx <= 1; dx++) {
                const int xx = wx + dx;
                if (xx < 0 || xx >= WW) continue;
                acc = fmaf(w[ch*9 + (dy+1)*3 + (dx+1)],
                           ub[(size_t)(yy*WW + xx)*HID + ch], acc);
            }
        }
        const float uc = ub[(size_t)n*HID + ch];
        hb[((size_t)b*NN + n)*HID + ch] = fmaf(mg[ch], acc, uc);
    }
}

// ---------------- SE: spatial mean ----------------
__global__ void __launch_bounds__(384) se_reduce_k(const float* __restrict__ y,
                                                   float* __restrict__ s0)
{
    const int b = blockIdx.x, c = threadIdx.x;
    const float* p = y + (size_t)b * NN * CC + c;
    float a0 = 0, a1 = 0, a2 = 0, a3 = 0;
    for (int n = 0; n < NN; n += 4) {
        a0 += p[(size_t)(n+0)*CC];
        a1 += p[(size_t)(n+1)*CC];
        a2 += p[(size_t)(n+2)*CC];
        a3 += p[(size_t)(n+3)*CC];
    }
    s0[b*CC + c] = (a0 + a1 + a2 + a3) * (1.f/NN);
}

// ---------------- SE: tiny MLP (reduce->relu->expand->sigmoid) ----------------
__global__ void __launch_bounds__(128) se_mlp_k(const float* __restrict__ s0,
                                                const float* __restrict__ rw,
                                                const float* __restrict__ rb,
                                                const float* __restrict__ ew,
                                                const float* __restrict__ eb,
                                                float* __restrict__ s2)
{
    __shared__ float s[CC];
    __shared__ float t[RD];
    const int b = blockIdx.x, tid = threadIdx.x;
    s[tid]     = s0[b*CC + tid];
    s[tid+128] = s0[b*CC + tid + 128];
    s[tid+256] = s0[b*CC + tid + 256];
    __syncthreads();
    if (tid < RD) {
        float a = rb[tid];
        for (int c = 0; c < CC; c++) a = fmaf(s[c], rw[c*RD + tid], a);
        t[tid] = fmaxf(a, 0.f);
    }
    __syncthreads();
    for (int c = tid; c < CC; c += 128) {
        float a = eb[c];
        for (int r = 0; r < RD; r++) a = fmaf(t[r], ew[r*CC + c], a);
        s2[b*CC + c] = 1.f / (1.f + __expf(-a));
    }
}

// ---------------- final: out = x1 + gamma2 * y * s2[b,c] ----------------
__global__ void __launch_bounds__(256) final_k(const float* __restrict__ x1,
                                               const float* __restrict__ y,
                                               const float* __restrict__ g2,
                                               const float* __restrict__ s2,
                                               float* __restrict__ out)
{
    const size_t i = (size_t)blockIdx.x * 256 + threadIdx.x;
    const int c = (int)(i % CC);
    const int b = (int)(i / ((size_t)NN * CC));
    out[i] = fmaf(g2[c], y[i] * s2[b*CC + c], x1[i]);
}

// ---------------- launch ----------------
static float* symaddr(const void* sym)
{
    void* p = nullptr;
    cudaGetSymbolAddress(&p, sym);
    return (float*)p;
}

extern "C" void kernel_launch(void* const* d_in, const int* in_sizes, int n_in,
                              void* d_out, int out_size)
{
    const float* x       = (const float*)d_in[0];
    // d_in[1], d_in[2] = H, W (fixed 28x28)
    const float* norm1_g = (const float*)d_in[3];
    const float* norm1_b = (const float*)d_in[4];
    const float* q_w     = (const float*)d_in[5];
    const float* q_b     = (const float*)d_in[6];
    const float* kv_w    = (const float*)d_in[7];
    const float* kv_b    = (const float*)d_in[8];
    const float* proj_w  = (const float*)d_in[9];
    const float* proj_b  = (const float*)d_in[10];
    const float* gamma1  = (const float*)d_in[11];
    const float* norm2_g = (const float*)d_in[12];
    const float* norm2_b = (const float*)d_in[13];
    const float* fc1_w   = (const float*)d_in[14];
    const float* fc1_b   = (const float*)d_in[15];
    const float* dw_w    = (const float*)d_in[16];
    const float* dw_b    = (const float*)d_in[17];
    const float* mlp_g   = (const float*)d_in[18];
    const float* fc2_w   = (const float*)d_in[19];
    const float* fc2_b   = (const float*)d_in[20];
    const float* se_rw   = (const float*)d_in[21];
    const float* se_rb   = (const float*)d_in[22];
    const float* se_ew   = (const float*)d_in[23];
    const float* se_eb   = (const float*)d_in[24];
    const float* gamma2  = (const float*)d_in[25];
    float* out = (float*)d_out;

    float* h1 = symaddr(g_h1);
    float* qb = symaddr(g_q);
    float* kv = symaddr(g_kv);
    float* S  = symaddr(g_S);
    float* ob = symaddr(g_o);
    float* x1 = symaddr(g_x1);
    float* h2 = symaddr(g_h2);
    float* u  = symaddr(g_u);
    float* hb = symaddr(g_hb);
    float* yb = symaddr(g_y);
    float* s0 = symaddr(g_s0);
    float* s2 = symaddr(g_s2);

    // --- attention branch ---
    ln_k<<<ROWS, 128>>>(x, norm1_g, norm1_b, h1);
    sgemm_k<0><<<dim3(CC/128, ROWS/128), 256>>>(h1, q_w, q_b, nullptr, nullptr, qb, ROWS, CC, CC);
    sgemm_k<0><<<dim3(2*CC/128, ROWS/128), 256>>>(h1, kv_w, kv_b, nullptr, nullptr, kv, ROWS, 2*CC, CC);

    const int nQ = (NN + 63) / 64;   // 13
    attn_scores_k<<<dim3(nQ, nQ, BH), 256>>>(qb, kv, S);
    softmax_k<<<dim3(NN, BH), 256>>>(S);
    attn_av_k<<<dim3(nQ, BH), 256>>>(S, kv, ob);

    sgemm_k<1><<<dim3(CC/128, ROWS/128), 256>>>(ob, proj_w, proj_b, x, gamma1, x1, ROWS, CC, CC);

    // --- SEMlp branch ---
    ln_k<<<ROWS, 128>>>(x1, norm2_g, norm2_b, h2);
    sgemm_k<0><<<dim3(HID/128, ROWS/128), 256>>>(h2, fc1_w, fc1_b, nullptr, nullptr, u, ROWS, HID, CC);
    dwconv_k<<<dim3(NN, BB), 256>>>(u, dw_w, dw_b, mlp_g, hb);
    sgemm_k<0><<<dim3(CC/128, ROWS/128), 256>>>(hb, fc2_w, fc2_b, nullptr, nullptr, yb, ROWS, CC, HID);

    se_reduce_k<<<BB, 384>>>(yb, s0);
    se_mlp_k<<<BB, 128>>>(s0, se_rw, se_rb, se_ew, se_eb, s2);

    final_k<<<(unsigned)(((size_t)ROWS*CC)/256), 256>>>(x1, yb, gamma2, s2, out);
}

// round 5
// speedup vs baseline: 1.2302x; 1.2302x over previous
#include <cuda_runtime.h>
#include <cstdint>
#include <cstddef>

// ---------------- problem constants ----------------
#define BB   16
#define NN   784
#define CC   384
#define HEADS 8
#define DH   48
#define HID  1536
#define RD   96
#define HH   28
#define WW   28
#define ROWS (BB*NN)          // 12544
#define BH   (BB*HEADS)       // 128

// ---------------- scratch (static device memory; allocation-free) ----------------
__device__ float g_h1[(size_t)ROWS*CC];
__device__ float g_q [(size_t)ROWS*CC];
__device__ float g_kv[(size_t)ROWS*2*CC];
__device__ float g_o [(size_t)ROWS*CC];
__device__ float g_x1[(size_t)ROWS*CC];
__device__ float g_h2[(size_t)ROWS*CC];
__device__ float g_u [(size_t)ROWS*HID];
__device__ float g_hb[(size_t)ROWS*HID];
__device__ float g_y [(size_t)ROWS*CC];
__device__ float g_s0[BB*CC];
__device__ float g_s2[BB*CC];

// ---------------- LayerNorm: one CTA (128 thr) per row of 384 ----------------
__global__ void __launch_bounds__(128) ln_k(const float* __restrict__ x,
                                            const float* __restrict__ g,
                                            const float* __restrict__ be,
                                            float* __restrict__ y)
{
    const int row = blockIdx.x;
    const int tid = threadIdx.x;
    const float* xr = x + (size_t)row * CC;
    float a = xr[tid], b2 = xr[tid+128], c = xr[tid+256];
    float s = a + b2 + c;
    float ss = a*a + b2*b2 + c*c;
    #pragma unroll
    for (int o = 16; o; o >>= 1) {
        s  += __shfl_xor_sync(0xffffffffu, s,  o);
        ss += __shfl_xor_sync(0xffffffffu, ss, o);
    }
    __shared__ float rs[4], rss[4];
    if ((tid & 31) == 0) { rs[tid>>5] = s; rss[tid>>5] = ss; }
    __syncthreads();
    s  = rs[0]+rs[1]+rs[2]+rs[3];
    ss = rss[0]+rss[1]+rss[2]+rss[3];
    const float m   = s * (1.f/CC);
    const float var = ss * (1.f/CC) - m*m;
    const float r   = rsqrtf(var + 1e-5f);
    float* yr = y + (size_t)row * CC;
    yr[tid]     = (a  - m)*r*g[tid]     + be[tid];
    yr[tid+128] = (b2 - m)*r*g[tid+128] + be[tid+128];
    yr[tid+256] = (c  - m)*r*g[tid+256] + be[tid+256];
}

// ---------------- 128x128x8 SGEMM, fp32, double-buffered ----------------
template<int MODE>
__global__ void __launch_bounds__(256, 2) sgemm_k(const float* __restrict__ A,
                                                  const float* __restrict__ B,
                                                  const float* __restrict__ bias,
                                                  const float* __restrict__ res,
                                                  const float* __restrict__ gamma,
                                                  float* __restrict__ C,
                                                  int M, int N, int K)
{
    __shared__ float As[2][8][128];
    __shared__ float Bs[2][8][128];
    const int tid = threadIdx.x;
    const int m0 = blockIdx.y * 128, n0 = blockIdx.x * 128;
    const int arow = tid >> 1, acol = (tid & 1) << 2;
    const int brow = tid >> 5, bcol = (tid & 31) << 2;
    const float* Ap = A + (size_t)(m0 + arow) * K + acol;
    const float* Bp = B + (size_t)brow * N + n0 + bcol;

    float4 av = *(const float4*)Ap;
    float4 bv = *(const float4*)Bp;
    As[0][acol+0][arow] = av.x; As[0][acol+1][arow] = av.y;
    As[0][acol+2][arow] = av.z; As[0][acol+3][arow] = av.w;
    *(float4*)&Bs[0][brow][bcol] = bv;
    __syncthreads();

    const int tx = (tid & 15) << 3, ty = (tid >> 4) << 3;
    float acc[8][8] = {};
    const int nk = K >> 3;
    for (int t = 1; t <= nk; t++) {
        const int cur = (t - 1) & 1, nxt = t & 1;
        if (t < nk) {
            av = *(const float4*)(Ap + t * 8);
            bv = *(const float4*)(Bp + (size_t)t * 8 * N);
        }
        #pragma unroll
        for (int kk = 0; kk < 8; kk++) {
            float af[8], bf[8];
            *(float4*)&af[0] = *(const float4*)&As[cur][kk][ty];
            *(float4*)&af[4] = *(const float4*)&As[cur][kk][ty+4];
            *(float4*)&bf[0] = *(const float4*)&Bs[cur][kk][tx];
            *(float4*)&bf[4] = *(const float4*)&Bs[cur][kk][tx+4];
            #pragma unroll
            for (int i = 0; i < 8; i++)
                #pragma unroll
                for (int j = 0; j < 8; j++)
                    acc[i][j] = fmaf(af[i], bf[j], acc[i][j]);
        }
        if (t < nk) {
            As[nxt][acol+0][arow] = av.x; As[nxt][acol+1][arow] = av.y;
            As[nxt][acol+2][arow] = av.z; As[nxt][acol+3][arow] = av.w;
            *(float4*)&Bs[nxt][brow][bcol] = bv;
        }
        __syncthreads();
    }

    #pragma unroll
    for (int i = 0; i < 8; i++) {
        const int m = m0 + ty + i;
        #pragma unroll
        for (int j = 0; j < 8; j++) {
            const int n = n0 + tx + j;
            float v = acc[i][j] + bias[n];
            if (MODE == 1) v = res[(size_t)m * N + n] + gamma[n] * v;
            C[(size_t)m * N + n] = v;
        }
    }
}

// ---------------- fused flash attention ----------------
// One CTA = one (q-tile of 64 rows, b, h). Online softmax, O accumulated in
// registers; S never touches global memory.
// smem: Qs[DH][64] | Ks[DH][64] | Vs[64][DH] | Ps[64][65]  = 53504 B
__global__ void __launch_bounds__(256) flash_k(const float* __restrict__ qg,
                                               const float* __restrict__ kvg,
                                               float* __restrict__ o)
{
    extern __shared__ float sm[];
    float* Qs = sm;               // [DH][64]
    float* Ks = Qs + DH * 64;     // [DH][64]
    float* Vs = Ks + DH * 64;     // [64][DH]
    float* Ps = Vs + 64 * DH;     // [64][65]

    const int tid = threadIdx.x;
    const int bh = blockIdx.y, b = bh >> 3, h = bh & 7;
    const int q0 = blockIdx.x * 64;
    const float scale = rsqrtf((float)DH);

    // load Q tile (transposed, pre-scaled)
    for (int e = tid; e < 64 * DH; e += 256) {
        const int r = e / DH, c = e % DH;
        const int qn = q0 + r;
        Qs[c * 64 + r] = (qn < NN) ? qg[((size_t)(b * NN + qn)) * CC + h * DH + c] * scale : 0.f;
    }

    const int tx = (tid & 15) << 2;   // S-tile cols (4 per thread)
    const int ty = (tid >> 4) << 2;   // rows (4 per thread, same rows for PV)
    const int vx = (tid & 15) * 3;    // O cols (3 per thread)

    float m[4] = {-1e30f, -1e30f, -1e30f, -1e30f};
    float l[4] = {0.f, 0.f, 0.f, 0.f};
    float acc[4][3] = {};

    for (int kc = 0; kc < NN; kc += 64) {
        __syncthreads();   // prior PV done reading Ks/Vs (no-op first iter)
        // load K chunk (transposed) + V chunk
        for (int e = tid; e < 64 * DH; e += 256) {
            const int r = e / DH, c = e % DH;
            const int kn = kc + r;
            const float* base = kvg + ((size_t)(b * NN + kn)) * 2 * CC;
            const bool ok = (kn < NN);
            Ks[c * 64 + r] = ok ? base[h * DH + c] : 0.f;
            Vs[r * DH + c] = ok ? base[CC + h * DH + c] : 0.f;
        }
        __syncthreads();

        // S tile: 4x4 per thread
        float s4[4][4] = {};
        #pragma unroll
        for (int kk = 0; kk < DH; kk++) {
            float af[4], bf[4];
            *(float4*)af = *(const float4*)&Qs[kk * 64 + ty];
            *(float4*)bf = *(const float4*)&Ks[kk * 64 + tx];
            #pragma unroll
            for (int i = 0; i < 4; i++)
                #pragma unroll
                for (int j = 0; j < 4; j++)
                    s4[i][j] = fmaf(af[i], bf[j], s4[i][j]);
        }
        // mask invalid key columns (tail chunk)
        #pragma unroll
        for (int j = 0; j < 4; j++)
            if (kc + tx + j >= NN) {
                #pragma unroll
                for (int i = 0; i < 4; i++) s4[i][j] = -1e30f;
            }

        // online softmax per row (16-lane row groups are warp-aligned)
        #pragma unroll
        for (int i = 0; i < 4; i++) {
            float cm = fmaxf(fmaxf(s4[i][0], s4[i][1]), fmaxf(s4[i][2], s4[i][3]));
            #pragma unroll
            for (int off = 1; off < 16; off <<= 1)
                cm = fmaxf(cm, __shfl_xor_sync(0xffffffffu, cm, off));
            const float mn = fmaxf(m[i], cm);
            const float al = __expf(m[i] - mn);
            float rs = 0.f;
            #pragma unroll
            for (int j = 0; j < 4; j++) {
                const float p = __expf(s4[i][j] - mn);
                s4[i][j] = p;
                rs += p;
            }
            #pragma unroll
            for (int off = 1; off < 16; off <<= 1)
                rs += __shfl_xor_sync(0xffffffffu, rs, off);
            l[i] = l[i] * al + rs;
            m[i] = mn;
            acc[i][0] *= al; acc[i][1] *= al; acc[i][2] *= al;
            #pragma unroll
            for (int j = 0; j < 4; j++)
                Ps[(tx + j) * 65 + ty + i] = s4[i][j];
        }
        __syncthreads();

        // O += P @ V  (4 rows x 3 cols per thread)
        #pragma unroll 8
        for (int kk = 0; kk < 64; kk++) {
            float pf[4];
            pf[0] = Ps[kk * 65 + ty + 0];
            pf[1] = Ps[kk * 65 + ty + 1];
            pf[2] = Ps[kk * 65 + ty + 2];
            pf[3] = Ps[kk * 65 + ty + 3];
            const float v0 = Vs[kk * DH + vx + 0];
            const float v1 = Vs[kk * DH + vx + 1];
            const float v2 = Vs[kk * DH + vx + 2];
            #pragma unroll
            for (int i = 0; i < 4; i++) {
                acc[i][0] = fmaf(pf[i], v0, acc[i][0]);
                acc[i][1] = fmaf(pf[i], v1, acc[i][1]);
                acc[i][2] = fmaf(pf[i], v2, acc[i][2]);
            }
        }
    }

    #pragma unroll
    for (int i = 0; i < 4; i++) {
        const int qn = q0 + ty + i;
        if (qn >= NN) continue;
        const float inv = 1.f / l[i];
        #pragma unroll
        for (int j = 0; j < 3; j++)
            o[((size_t)(b * NN + qn)) * CC + h * DH + vx + j] = acc[i][j] * inv;
    }
}

// ---------------- depthwise 3x3 conv + bias + mlp_gamma*dw + u ----------------
__global__ void __launch_bounds__(256) dwconv_k(const float* __restrict__ u,
                                                const float* __restrict__ w,
                                                const float* __restrict__ wb,
                                                const float* __restrict__ mg,
                                                float* __restrict__ hb)
{
    const int n = blockIdx.x, b = blockIdx.y;
    const int hy = n / WW, wx = n % WW;
    const float* ub = u + (size_t)b * NN * HID;
    for (int ch = threadIdx.x; ch < HID; ch += 256) {
        float acc = wb[ch];
        #pragma unroll
        for (int dy = -1; dy <= 1; dy++) {
            const int yy = hy + dy;
            if (yy < 0 || yy >= HH) continue;
            #pragma unroll
            for (int dx = -1; dx <= 1; dx++) {
                const int xx = wx + dx;
                if (xx < 0 || xx >= WW) continue;
                acc = fmaf(w[ch*9 + (dy+1)*3 + (dx+1)],
                           ub[(size_t)(yy*WW + xx)*HID + ch], acc);
            }
        }
        const float uc = ub[(size_t)n*HID + ch];
        hb[((size_t)b*NN + n)*HID + ch] = fmaf(mg[ch], acc, uc);
    }
}

// ---------------- SE: spatial mean ----------------
__global__ void __launch_bounds__(384) se_reduce_k(const float* __restrict__ y,
                                                   float* __restrict__ s0)
{
    const int b = blockIdx.x, c = threadIdx.x;
    const float* p = y + (size_t)b * NN * CC + c;
    float a0 = 0, a1 = 0, a2 = 0, a3 = 0;
    for (int n = 0; n < NN; n += 4) {
        a0 += p[(size_t)(n+0)*CC];
        a1 += p[(size_t)(n+1)*CC];
        a2 += p[(size_t)(n+2)*CC];
        a3 += p[(size_t)(n+3)*CC];
    }
    s0[b*CC + c] = (a0 + a1 + a2 + a3) * (1.f/NN);
}

// ---------------- SE: tiny MLP ----------------
__global__ void __launch_bounds__(128) se_mlp_k(const float* __restrict__ s0,
                                                const float* __restrict__ rw,
                                                const float* __restrict__ rb,
                                                const float* __restrict__ ew,
                                                const float* __restrict__ eb,
                                                float* __restrict__ s2)
{
    __shared__ float s[CC];
    __shared__ float t[RD];
    const int b = blockIdx.x, tid = threadIdx.x;
    s[tid]     = s0[b*CC + tid];
    s[tid+128] = s0[b*CC + tid + 128];
    s[tid+256] = s0[b*CC + tid + 256];
    __syncthreads();
    if (tid < RD) {
        float a = rb[tid];
        for (int c = 0; c < CC; c++) a = fmaf(s[c], rw[c*RD + tid], a);
        t[tid] = fmaxf(a, 0.f);
    }
    __syncthreads();
    for (int c = tid; c < CC; c += 128) {
        float a = eb[c];
        for (int r = 0; r < RD; r++) a = fmaf(t[r], ew[r*CC + c], a);
        s2[b*CC + c] = 1.f / (1.f + __expf(-a));
    }
}

// ---------------- final: out = x1 + gamma2 * y * s2[b,c] ----------------
__global__ void __launch_bounds__(256) final_k(const float* __restrict__ x1,
                                               const float* __restrict__ y,
                                               const float* __restrict__ g2,
                                               const float* __restrict__ s2,
                                               float* __restrict__ out)
{
    const size_t i = (size_t)blockIdx.x * 256 + threadIdx.x;
    const int c = (int)(i % CC);
    const int b = (int)(i / ((size_t)NN * CC));
    out[i] = fmaf(g2[c], y[i] * s2[b*CC + c], x1[i]);
}

// ---------------- launch ----------------
static float* symaddr(const void* sym)
{
    void* p = nullptr;
    cudaGetSymbolAddress(&p, sym);
    return (float*)p;
}

extern "C" void kernel_launch(void* const* d_in, const int* in_sizes, int n_in,
                              void* d_out, int out_size)
{
    const float* x       = (const float*)d_in[0];
    const float* norm1_g = (const float*)d_in[3];
    const float* norm1_b = (const float*)d_in[4];
    const float* q_w     = (const float*)d_in[5];
    const float* q_b     = (const float*)d_in[6];
    const float* kv_w    = (const float*)d_in[7];
    const float* kv_b    = (const float*)d_in[8];
    const float* proj_w  = (const float*)d_in[9];
    const float* proj_b  = (const float*)d_in[10];
    const float* gamma1  = (const float*)d_in[11];
    const float* norm2_g = (const float*)d_in[12];
    const float* norm2_b = (const float*)d_in[13];
    const float* fc1_w   = (const float*)d_in[14];
    const float* fc1_b   = (const float*)d_in[15];
    const float* dw_w    = (const float*)d_in[16];
    const float* dw_b    = (const float*)d_in[17];
    const float* mlp_g   = (const float*)d_in[18];
    const float* fc2_w   = (const float*)d_in[19];
    const float* fc2_b   = (const float*)d_in[20];
    const float* se_rw   = (const float*)d_in[21];
    const float* se_rb   = (const float*)d_in[22];
    const float* se_ew   = (const float*)d_in[23];
    const float* se_eb   = (const float*)d_in[24];
    const float* gamma2  = (const float*)d_in[25];
    float* out = (float*)d_out;

    float* h1 = symaddr(g_h1);
    float* qb = symaddr(g_q);
    float* kv = symaddr(g_kv);
    float* ob = symaddr(g_o);
    float* x1 = symaddr(g_x1);
    float* h2 = symaddr(g_h2);
    float* u  = symaddr(g_u);
    float* hb = symaddr(g_hb);
    float* yb = symaddr(g_y);
    float* s0 = symaddr(g_s0);
    float* s2 = symaddr(g_s2);

    // --- attention branch ---
    ln_k<<<ROWS, 128>>>(x, norm1_g, norm1_b, h1);
    sgemm_k<0><<<dim3(CC/128, ROWS/128), 256>>>(h1, q_w, q_b, nullptr, nullptr, qb, ROWS, CC, CC);
    sgemm_k<0><<<dim3(2*CC/128, ROWS/128), 256>>>(h1, kv_w, kv_b, nullptr, nullptr, kv, ROWS, 2*CC, CC);

    const int nQ = (NN + 63) / 64;   // 13
    const size_t shm = (size_t)(2 * DH * 64 + 64 * DH + 64 * 65) * sizeof(float);  // 53504
    cudaFuncSetAttribute(flash_k, cudaFuncAttributeMaxDynamicSharedMemorySize, (int)shm);
    flash_k<<<dim3(nQ, BH), 256, shm>>>(qb, kv, ob);

    sgemm_k<1><<<dim3(CC/128, ROWS/128), 256>>>(ob, proj_w, proj_b, x, gamma1, x1, ROWS, CC, CC);

    // --- SEMlp branch ---
    ln_k<<<ROWS, 128>>>(x1, norm2_g, norm2_b, h2);
    sgemm_k<0><<<dim3(HID/128, ROWS/128), 256>>>(h2, fc1_w, fc1_b, nullptr, nullptr, u, ROWS, HID, CC);
    dwconv_k<<<dim3(NN, BB), 256>>>(u, dw_w, dw_b, mlp_g, hb);
    sgemm_k<0><<<dim3(CC/128, ROWS/128), 256>>>(hb, fc2_w, fc2_b, nullptr, nullptr, yb, ROWS, CC, HID);

    se_reduce_k<<<BB, 384>>>(yb, s0);
    se_mlp_k<<<BB, 128>>>(s0, se_rw, se_rb, se_ew, se_eb, s2);

    final_k<<<(unsigned)(((size_t)ROWS*CC)/256), 256>>>(x1, yb, gamma2, s2, out);
}